// round 11
// baseline (speedup 1.0000x reference)
#include <cuda_runtime.h>
#include <math.h>

#define IMG_N 16
#define IMG_H 1024
#define IMG_W 1024
#define WS    11
#define OUT_H (IMG_H - WS + 1)   // 1014
#define OUT_W (IMG_W - WS + 1)   // 1014

#define NTHR  288                // 9 warps
#define OH    12                 // output rows per chunk
#define NCHUNK 4                 // chunks per block (48 output rows)
#define SEGR  (OH * NCHUNK)      // 48
#define NCK   24                 // chunks per row (NTHR/OH)
#define CW    11                 // outputs per thread
#define OWT   (NCK * CW)         // 264 output cols per tile
#define ICT   (OWT + WS - 1)     // 274 input cols per tile
#define PAB   275                // float4 pitch (quarter-warp conflict-free, any PAB)
#define PC    296                // float pitch (== 8 mod 32 -> warp conflict-free)
#define GX    4                  // ceil(1014/264)
#define GYS   22                 // ceil(1014/48)

#define AB_BYTES (OH * PAB * 16)             // 52800
#define C_OFF    AB_BYTES
#define SMEM_BYTES (C_OFF + OH * PC * 4)     // 67008 -> 3 CTAs/SM

typedef unsigned long long ull;

// ---------------- packed f32x2 helpers (phase 2 only) ----------------
__device__ __forceinline__ ull f2add(ull a, ull b) {
    ull r; asm("add.rn.f32x2 %0, %1, %2;" : "=l"(r) : "l"(a), "l"(b)); return r;
}
__device__ __forceinline__ ull f2fma(ull a, ull b, ull c) {
    ull r; asm("fma.rn.f32x2 %0, %1, %2, %3;" : "=l"(r) : "l"(a), "l"(b), "l"(c)); return r;
}
__device__ __forceinline__ void f2unpack(ull v, float& lo, float& hi) {
    asm("mov.b64 {%0, %1}, %2;" : "=f"(lo), "=f"(hi) : "l"(v));
}
#define F2_NEG1 0xBF800000BF800000ULL
#define F2_SGN  0x8000000080000000ULL

// ---------------- device globals ----------
__device__ unsigned g_min1u, g_max1u, g_min2u, g_max2u;
__device__ double   g_sum;
__device__ float    g_k1, g_b1, g_k2, g_b2, g_u, g_invs, g_thr;

__device__ __forceinline__ unsigned fenc(float f) {
    unsigned b = __float_as_uint(f);
    return (b & 0x80000000u) ? ~b : (b | 0x80000000u);
}
__device__ __forceinline__ float fdec(unsigned u) {
    unsigned b = (u & 0x80000000u) ? (u ^ 0x80000000u) : ~u;
    return __uint_as_float(b);
}

__global__ void init_k() {
    g_min1u = 0xFFFFFFFFu; g_max1u = 0u;
    g_min2u = 0xFFFFFFFFu; g_max2u = 0u;
    g_sum   = 0.0;
}

// ---------------- pass 1: global min/max --------------------
__global__ void minmax_k(const float4* __restrict__ a,
                         const float4* __restrict__ b, int n4) {
    float mn1 =  3.4e38f, mx1 = -3.4e38f;
    float mn2 =  3.4e38f, mx2 = -3.4e38f;
    for (int i = blockIdx.x * blockDim.x + threadIdx.x; i < n4;
         i += gridDim.x * blockDim.x) {
        float4 v = a[i];
        mn1 = fminf(mn1, fminf(fminf(v.x, v.y), fminf(v.z, v.w)));
        mx1 = fmaxf(mx1, fmaxf(fmaxf(v.x, v.y), fmaxf(v.z, v.w)));
        float4 w = b[i];
        mn2 = fminf(mn2, fminf(fminf(w.x, w.y), fminf(w.z, w.w)));
        mx2 = fmaxf(mx2, fmaxf(fmaxf(w.x, w.y), fmaxf(w.z, w.w)));
    }
    #pragma unroll
    for (int o = 16; o; o >>= 1) {
        mn1 = fminf(mn1, __shfl_down_sync(0xffffffffu, mn1, o));
        mx1 = fmaxf(mx1, __shfl_down_sync(0xffffffffu, mx1, o));
        mn2 = fminf(mn2, __shfl_down_sync(0xffffffffu, mn2, o));
        mx2 = fmaxf(mx2, __shfl_down_sync(0xffffffffu, mx2, o));
    }
    __shared__ float s0[8], s1[8], s2[8], s3[8];
    int lane = threadIdx.x & 31, warp = threadIdx.x >> 5;
    if (lane == 0) { s0[warp] = mn1; s1[warp] = mx1; s2[warp] = mn2; s3[warp] = mx2; }
    __syncthreads();
    if (threadIdx.x == 0) {
        for (int w = 1; w < 8; w++) {
            mn1 = fminf(mn1, s0[w]); mx1 = fmaxf(mx1, s1[w]);
            mn2 = fminf(mn2, s2[w]); mx2 = fmaxf(mx2, s3[w]);
        }
        atomicMin(&g_min1u, fenc(mn1)); atomicMax(&g_max1u, fenc(mx1));
        atomicMin(&g_min2u, fenc(mn2)); atomicMax(&g_max2u, fenc(mx2));
    }
}

// ---------------- pass 2: constants ------------
__global__ void prep_k() {
    float mn1 = fdec(g_min1u), mx1 = fdec(g_max1u);
    float mn2 = fdec(g_min2u), mx2 = fdec(g_max2u);
    float k1 = 255.0f / (mx1 - mn1 + 1e-6f);
    float k2 = 255.0f / (mx2 - mn2 + 1e-6f);
    g_k1 = k1; g_b1 = -mn1 * k1;
    g_k2 = k2; g_b2 = -mn2 * k2;
    double csf = 100.0 * 2.6 * (0.0192 + 0.114 * 16.0) * exp(-pow(0.114 * 16.0, 1.1));
    double u   = 128.0 / (1.4 * csf);
    double sg  = u / 3.0;
    g_u    = (float)u;
    g_invs = (float)(1.0 / (sg * sqrt(2.0)));
    double st = u + 4.0 * sg * sqrt(2.0);   // erf arg >= 4 => saturates to 1.0f
    g_thr = (float)(st * st);
}

// ---------------- exact per-pixel (fallback only) ----------------
__device__ float px_exact(float v1, float v2, float cv,
                          float thr, float U, float IS) {
    if (fminf(v1, v2) > thr) {
        float p = (v1 + 1e-6f) * (v2 + 1e-6f);
        float s = p * rsqrtf(p);
        return __fdividef(cv + 10.0f, s + 10.0f);
    }
    float sg1 = sqrtf(fmaxf(v1, 0.0f) + 1e-6f);
    float sg2 = sqrtf(fmaxf(v2, 0.0f) + 1e-6f);
    float pA = 0.5f * (1.0f + erff((sg1 - U) * IS));
    float pB = 0.5f * (1.0f + erff((sg2 - U) * IS));
    float num = 2.0f * pA * pB + 0.01f;
    float den = pA * pA + pB * pB + 0.01f;
    return (num / den) * ((cv + 10.0f) / (sg1 * sg2 + 10.0f));
}

// exact chunk recompute (never taken on this data)
__device__ __noinline__ float exact_chunk(const float4* __restrict__ AB,
                                          const float* __restrict__ C,
                                          int r, int x0, bool rowok, int maxi,
                                          float thr, float U, float IS) {
    float acc = 0.0f;
    if (!rowok) return 0.0f;
    for (int j = 0; j < CW; j++) {
        if (j >= maxi) break;
        float h0 = 0.f, h1 = 0.f, h2 = 0.f, h3 = 0.f, h4 = 0.f;
        for (int k = 0; k < WS; k++) {
            float4 t = AB[r * PAB + x0 + j + k];
            h0 += t.x; h1 += t.y; h2 += t.z; h3 += t.w;
            h4 += C[r * PC + x0 + j + k];
        }
        float v1 = fmaf(-h0, h0, h2);
        float v2 = fmaf(-h1, h1, h3);
        float cv = fmaf(-h0, h1, h4);
        acc += px_exact(v1, v2, cv, thr, U, IS);
    }
    return acc;
}

// ---------------- phase 1: streamed vertical chunk (scalar) ----------
template<int NR, int START, bool FULL>
__device__ __forceinline__ void vchunk(
    const float* __restrict__ p1, const float* __restrict__ p2,
    int tid, int rowlim, bool colok,
    float k1, float b1, float k2, float b2, float wgt,
    float (&r1)[WS], float (&r2)[WS],
    float& s1, float& s2, float& s11, float& s22, float& s12,
    float4* __restrict__ AB, float* __restrict__ C)
{
    #pragma unroll
    for (int j = 0; j < NR; j++) {
        const int R = START + j;
        float v1, v2;
        if (FULL) {
            v1 = __ldg(p1 + R * IMG_W);
            v2 = __ldg(p2 + R * IMG_W);
        } else {
            bool ok = colok && (R < rowlim);
            v1 = ok ? __ldg(p1 + R * IMG_W) : 0.0f;
            v2 = ok ? __ldg(p2 + R * IMG_W) : 0.0f;
        }
        float x1 = fmaf(v1, k1, b1);
        float x2 = fmaf(v2, k2, b2);
        s1 += x1; s2 += x2;
        s11 = fmaf(x1, x1, s11);
        s22 = fmaf(x2, x2, s22);
        s12 = fmaf(x1, x2, s12);
        if (R >= WS - 1) {
            const int lr = (R - (WS - 1)) % OH;
            AB[lr * PAB + tid] = make_float4(s1 * wgt, s2 * wgt, s11 * wgt, s22 * wgt);
            C[lr * PC + tid]   = s12 * wgt;
            float o1 = r1[(R + 1) % WS];
            float o2 = r2[(R + 1) % WS];
            s1 -= o1; s2 -= o2;
            s11 = fmaf(-o1, o1, s11);
            s22 = fmaf(-o2, o2, s22);
            s12 = fmaf(-o1, o2, s12);
        }
        r1[R % WS] = x1;
        r2[R % WS] = x2;
    }
}

// ---------------- phase 2: branch-free horizontal windows ----------------
template<bool FULL>
__device__ __forceinline__ float hchunk(const float4* __restrict__ AB,
                                        const float* __restrict__ C,
                                        int r, int x0,
                                        bool rowok, int maxi,
                                        float thr, float U, float IS,
                                        float& okmin)
{
    const ulonglong2* ABr = (const ulonglong2*)(AB + r * PAB + x0);
    const float*      Cr  = C + r * PC + x0;

    // tree warmup over first 10 columns
    ull hm, hv; float hc;
    {
        ulonglong2 t0 = ABr[0], t1 = ABr[1], t2 = ABr[2], t3 = ABr[3], t4 = ABr[4];
        ulonglong2 t5 = ABr[5], t6 = ABr[6], t7 = ABr[7], t8 = ABr[8], t9 = ABr[9];
        ull m01 = f2add(t0.x, t1.x), m23 = f2add(t2.x, t3.x);
        ull m45 = f2add(t4.x, t5.x), m67 = f2add(t6.x, t7.x);
        ull m89 = f2add(t8.x, t9.x);
        hm = f2add(f2add(f2add(m01, m23), f2add(m45, m67)), m89);
        ull v01 = f2add(t0.y, t1.y), v23 = f2add(t2.y, t3.y);
        ull v45 = f2add(t4.y, t5.y), v67 = f2add(t6.y, t7.y);
        ull v89 = f2add(t8.y, t9.y);
        hv = f2add(f2add(f2add(v01, v23), f2add(v45, v67)), v89);
        float c01 = Cr[0] + Cr[1], c23 = Cr[2] + Cr[3];
        float c45 = Cr[4] + Cr[5], c67 = Cr[6] + Cr[7];
        float c89 = Cr[8] + Cr[9];
        hc = ((c01 + c23) + (c45 + c67)) + c89;
    }

    float acc = 0.0f;
    #pragma unroll
    for (int j = 0; j < CW; j++) {
        ulonglong2 t = ABr[j + WS - 1];
        float c = Cr[j + WS - 1];
        hm = f2add(hm, t.x); hv = f2add(hv, t.y); hc += c;

        ull v12 = f2fma(hm, hm ^ F2_SGN, hv);   // s - m*m
        float m1, m2, v1, v2;
        f2unpack(hm, m1, m2);
        f2unpack(v12, v1, v2);
        float cv = fmaf(-m1, m2, hc);

        // branch-free fast value (exact when window is saturated)
        float p = v1 * v2;
        float s = p * rsqrtf(p);                // sigma1*sigma2
        float fv = __fdividef(cv + 10.0f, s + 10.0f);

        float vmin = fminf(v1, v2);
        if (FULL) {
            okmin = fminf(okmin, vmin);
            acc += fv;
        } else {
            bool valid = rowok && (j < maxi);
            okmin = fminf(okmin, valid ? vmin : 3.4e38f);
            acc += valid ? fv : 0.0f;
        }

        ulonglong2 u = ABr[j];                  // tail re-read
        float cu = Cr[j];
        hm = f2fma(u.x, F2_NEG1, hm);
        hv = f2fma(u.y, F2_NEG1, hv);
        hc -= cu;
    }

    // chunk-level fallback: warp-uniform, never taken on this data
    if (!__all_sync(0xffffffffu, okmin > thr))
        acc = exact_chunk(AB, C, r, x0, rowok, maxi, thr, U, IS);
    return acc;
}

// ---------------- main body ----------------
template<bool FULL>
__device__ __forceinline__ float body(const float* __restrict__ p1,
                                      const float* __restrict__ p2,
                                      int tid, int ox0, int oy0, int rowlim,
                                      float4* __restrict__ AB,
                                      float* __restrict__ C)
{
    const float k1 = g_k1, b1 = g_b1, k2 = g_k2, b2 = g_b2;
    const float wgt = 1.0f / (float)(WS * WS);
    const float U = g_u, IS = g_invs, thr = g_thr;

    const int r  = tid / NCK;            // 0..11
    const int x0 = (tid % NCK) * CW;
    const int maxi = OUT_W - (ox0 + x0);
    const bool colok = FULL || (ox0 + tid < IMG_W);
    const bool p1ok = (tid < ICT);

    float r1[WS], r2[WS];
    float s1 = 0.f, s2 = 0.f, s11 = 0.f, s22 = 0.f, s12 = 0.f;
    float acc = 0.0f;
    float okmin = 3.4e38f;

    // chunk 0: rows 0..21
    if (p1ok)
        vchunk<OH + WS - 1, 0, FULL>(p1, p2, tid, rowlim, colok,
                                     k1, b1, k2, b2, wgt,
                                     r1, r2, s1, s2, s11, s22, s12, AB, C);
    __syncthreads();
    acc += hchunk<FULL>(AB, C, r, x0, oy0 + r < OUT_H, maxi, thr, U, IS, okmin);
    __syncthreads();

    // chunk 1: rows 22..33
    if (p1ok)
        vchunk<OH, OH + WS - 1, FULL>(p1, p2, tid, rowlim, colok,
                                      k1, b1, k2, b2, wgt,
                                      r1, r2, s1, s2, s11, s22, s12, AB, C);
    __syncthreads();
    acc += hchunk<FULL>(AB, C, r, x0, oy0 + OH + r < OUT_H, maxi, thr, U, IS, okmin);
    __syncthreads();

    // chunk 2: rows 34..45
    if (p1ok)
        vchunk<OH, 2 * OH + WS - 1, FULL>(p1, p2, tid, rowlim, colok,
                                          k1, b1, k2, b2, wgt,
                                          r1, r2, s1, s2, s11, s22, s12, AB, C);
    __syncthreads();
    acc += hchunk<FULL>(AB, C, r, x0, oy0 + 2 * OH + r < OUT_H, maxi, thr, U, IS, okmin);
    __syncthreads();

    // chunk 3: rows 46..57
    if (p1ok)
        vchunk<OH, 3 * OH + WS - 1, FULL>(p1, p2, tid, rowlim, colok,
                                          k1, b1, k2, b2, wgt,
                                          r1, r2, s1, s2, s11, s22, s12, AB, C);
    __syncthreads();
    acc += hchunk<FULL>(AB, C, r, x0, oy0 + 3 * OH + r < OUT_H, maxi, thr, U, IS, okmin);
    return acc;
}

__global__ __launch_bounds__(NTHR, 3)
void tmqi_k(const float* __restrict__ img1, const float* __restrict__ img2) {
    extern __shared__ char sm_[];
    float4* AB = (float4*)sm_;
    float*  C  = (float*)(sm_ + C_OFF);

    const int tid = threadIdx.x;
    const int ox0 = blockIdx.x * OWT;
    const int oy0 = blockIdx.y * SEGR;
    const int bz  = blockIdx.z;

    const float* p1 = img1 + (size_t)bz * IMG_H * IMG_W + (size_t)oy0 * IMG_W + ox0 + tid;
    const float* p2 = img2 + (size_t)bz * IMG_H * IMG_W + (size_t)oy0 * IMG_W + ox0 + tid;
    const int rowlim = IMG_H - oy0;

    const bool fullb = (blockIdx.x < GX - 1) && (oy0 + SEGR + WS - 1 <= IMG_H);

    float acc;
    if (fullb)
        acc = body<true>(p1, p2, tid, ox0, oy0, rowlim, AB, C);
    else
        acc = body<false>(p1, p2, tid, ox0, oy0, rowlim, AB, C);

    // --- block reduction (9 warps) ---
    #pragma unroll
    for (int o = 16; o; o >>= 1)
        acc += __shfl_down_sync(0xffffffffu, acc, o);
    __shared__ float red[9];
    if ((tid & 31) == 0) red[tid >> 5] = acc;
    __syncthreads();
    if (tid == 0) {
        float v = red[0];
        #pragma unroll
        for (int i = 1; i < 9; i++) v += red[i];
        atomicAdd(&g_sum, (double)v);
    }
}

__global__ void final_k(float* out) {
    out[0] = (float)(g_sum / ((double)IMG_N * OUT_H * OUT_W));
}

// ---------------- launch -----------------------------------------------
extern "C" void kernel_launch(void* const* d_in, const int* in_sizes, int n_in,
                              void* d_out, int out_size) {
    const float* img1 = (const float*)d_in[0];
    const float* img2 = (const float*)d_in[1];
    float* out = (float*)d_out;

    init_k<<<1, 1>>>();

    int n4 = (IMG_N * IMG_H * IMG_W) / 4;
    minmax_k<<<2048, 256>>>((const float4*)img1, (const float4*)img2, n4);

    prep_k<<<1, 1>>>();

    cudaFuncSetAttribute(tmqi_k, cudaFuncAttributeMaxDynamicSharedMemorySize,
                         SMEM_BYTES);
    dim3 grid(GX, GYS, IMG_N);   // (4, 22, 16) = 1408 blocks
    tmqi_k<<<grid, NTHR, SMEM_BYTES>>>(img1, img2);

    final_k<<<1, 1>>>(out);
}

// round 12
// speedup vs baseline: 1.0389x; 1.0389x over previous
#include <cuda_runtime.h>
#include <math.h>

#define IMG_N 16
#define IMG_H 1024
#define IMG_W 1024
#define WS    11
#define OUT_H (IMG_H - WS + 1)   // 1014
#define OUT_W (IMG_W - WS + 1)   // 1014

#define NTHR  288                // 9 warps
#define OH    12                 // output rows per chunk
#define NCHUNK 4                 // chunks per block (48 output rows)
#define SEGR  (OH * NCHUNK)      // 48
#define NCK   24                 // chunks per row (NTHR/OH)
#define CW    11                 // outputs per thread
#define OWT   (NCK * CW)         // 264 output cols per tile
#define ICT   (OWT + WS - 1)     // 274 input cols per tile
#define PAB   275                // float4 pitch (quarter-warp conflict-free, any PAB)
#define PC    296                // float pitch (== 8 mod 32 -> warp conflict-free)
#define GX    4                  // ceil(1014/264)
#define GYS   22                 // ceil(1014/48)

#define AB_BYTES (OH * PAB * 16)             // 52800
#define C_OFF    AB_BYTES
#define SMEM_BYTES (C_OFF + OH * PC * 4)     // 67008 -> 3 CTAs/SM

typedef unsigned long long ull;

// ---------------- packed f32x2 helpers (phase 2 only) ----------------
__device__ __forceinline__ ull f2add(ull a, ull b) {
    ull r; asm("add.rn.f32x2 %0, %1, %2;" : "=l"(r) : "l"(a), "l"(b)); return r;
}
__device__ __forceinline__ ull f2fma(ull a, ull b, ull c) {
    ull r; asm("fma.rn.f32x2 %0, %1, %2, %3;" : "=l"(r) : "l"(a), "l"(b), "l"(c)); return r;
}
__device__ __forceinline__ void f2unpack(ull v, float& lo, float& hi) {
    asm("mov.b64 {%0, %1}, %2;" : "=f"(lo), "=f"(hi) : "l"(v));
}
#define F2_NEG1 0xBF800000BF800000ULL
#define F2_SGN  0x8000000080000000ULL

// ---------------- device globals ----------
__device__ unsigned g_min1u, g_max1u, g_min2u, g_max2u;
__device__ double   g_sum;
__device__ float    g_k1, g_b1, g_k2, g_b2, g_u, g_invs, g_thr;

__device__ __forceinline__ unsigned fenc(float f) {
    unsigned b = __float_as_uint(f);
    return (b & 0x80000000u) ? ~b : (b | 0x80000000u);
}
__device__ __forceinline__ float fdec(unsigned u) {
    unsigned b = (u & 0x80000000u) ? (u ^ 0x80000000u) : ~u;
    return __uint_as_float(b);
}

__global__ void init_k() {
    g_min1u = 0xFFFFFFFFu; g_max1u = 0u;
    g_min2u = 0xFFFFFFFFu; g_max2u = 0u;
    g_sum   = 0.0;
}

// ---------------- pass 1: global min/max --------------------
__global__ void minmax_k(const float4* __restrict__ a,
                         const float4* __restrict__ b, int n4) {
    float mn1 =  3.4e38f, mx1 = -3.4e38f;
    float mn2 =  3.4e38f, mx2 = -3.4e38f;
    for (int i = blockIdx.x * blockDim.x + threadIdx.x; i < n4;
         i += gridDim.x * blockDim.x) {
        float4 v = a[i];
        mn1 = fminf(mn1, fminf(fminf(v.x, v.y), fminf(v.z, v.w)));
        mx1 = fmaxf(mx1, fmaxf(fmaxf(v.x, v.y), fmaxf(v.z, v.w)));
        float4 w = b[i];
        mn2 = fminf(mn2, fminf(fminf(w.x, w.y), fminf(w.z, w.w)));
        mx2 = fmaxf(mx2, fmaxf(fmaxf(w.x, w.y), fmaxf(w.z, w.w)));
    }
    #pragma unroll
    for (int o = 16; o; o >>= 1) {
        mn1 = fminf(mn1, __shfl_down_sync(0xffffffffu, mn1, o));
        mx1 = fmaxf(mx1, __shfl_down_sync(0xffffffffu, mx1, o));
        mn2 = fminf(mn2, __shfl_down_sync(0xffffffffu, mn2, o));
        mx2 = fmaxf(mx2, __shfl_down_sync(0xffffffffu, mx2, o));
    }
    __shared__ float s0[8], s1[8], s2[8], s3[8];
    int lane = threadIdx.x & 31, warp = threadIdx.x >> 5;
    if (lane == 0) { s0[warp] = mn1; s1[warp] = mx1; s2[warp] = mn2; s3[warp] = mx2; }
    __syncthreads();
    if (threadIdx.x == 0) {
        for (int w = 1; w < 8; w++) {
            mn1 = fminf(mn1, s0[w]); mx1 = fmaxf(mx1, s1[w]);
            mn2 = fminf(mn2, s2[w]); mx2 = fmaxf(mx2, s3[w]);
        }
        atomicMin(&g_min1u, fenc(mn1)); atomicMax(&g_max1u, fenc(mx1));
        atomicMin(&g_min2u, fenc(mn2)); atomicMax(&g_max2u, fenc(mx2));
    }
}

// ---------------- pass 2: constants ------------
__global__ void prep_k() {
    float mn1 = fdec(g_min1u), mx1 = fdec(g_max1u);
    float mn2 = fdec(g_min2u), mx2 = fdec(g_max2u);
    float k1 = 255.0f / (mx1 - mn1 + 1e-6f);
    float k2 = 255.0f / (mx2 - mn2 + 1e-6f);
    g_k1 = k1; g_b1 = -mn1 * k1;
    g_k2 = k2; g_b2 = -mn2 * k2;
    double csf = 100.0 * 2.6 * (0.0192 + 0.114 * 16.0) * exp(-pow(0.114 * 16.0, 1.1));
    double u   = 128.0 / (1.4 * csf);
    double sg  = u / 3.0;
    g_u    = (float)u;
    g_invs = (float)(1.0 / (sg * sqrt(2.0)));
    double st = u + 4.0 * sg * sqrt(2.0);   // erf arg >= 4 => saturates to 1.0f
    g_thr = (float)(st * st);
}

// ---------------- exact per-pixel (fallback only) ----------------
__device__ float px_exact(float v1, float v2, float cv,
                          float thr, float U, float IS) {
    if (fminf(v1, v2) > thr) {
        float p = (v1 + 1e-6f) * (v2 + 1e-6f);
        float s = p * rsqrtf(p);
        return __fdividef(cv + 10.0f, s + 10.0f);
    }
    float sg1 = sqrtf(fmaxf(v1, 0.0f) + 1e-6f);
    float sg2 = sqrtf(fmaxf(v2, 0.0f) + 1e-6f);
    float pA = 0.5f * (1.0f + erff((sg1 - U) * IS));
    float pB = 0.5f * (1.0f + erff((sg2 - U) * IS));
    float num = 2.0f * pA * pB + 0.01f;
    float den = pA * pA + pB * pB + 0.01f;
    return (num / den) * ((cv + 10.0f) / (sg1 * sg2 + 10.0f));
}

// exact chunk recompute (never taken on this data)
__device__ __noinline__ float exact_chunk(const float4* __restrict__ AB,
                                          const float* __restrict__ C,
                                          int r, int x0, bool rowok, int maxi,
                                          float thr, float U, float IS) {
    float acc = 0.0f;
    if (!rowok) return 0.0f;
    for (int j = 0; j < CW; j++) {
        if (j >= maxi) break;
        float h0 = 0.f, h1 = 0.f, h2 = 0.f, h3 = 0.f, h4 = 0.f;
        for (int k = 0; k < WS; k++) {
            float4 t = AB[r * PAB + x0 + j + k];
            h0 += t.x; h1 += t.y; h2 += t.z; h3 += t.w;
            h4 += C[r * PC + x0 + j + k];
        }
        float v1 = fmaf(-h0, h0, h2);
        float v2 = fmaf(-h1, h1, h3);
        float cv = fmaf(-h0, h1, h4);
        acc += px_exact(v1, v2, cv, thr, U, IS);
    }
    return acc;
}

// ---------------- phase 1: streamed vertical chunk (scalar) ----------
template<int NR, int START, bool FULL>
__device__ __forceinline__ void vchunk(
    const float* __restrict__ p1, const float* __restrict__ p2,
    int tid, int rowlim, bool colok,
    float k1, float b1, float k2, float b2, float wgt,
    float (&r1)[WS], float (&r2)[WS],
    float& s1, float& s2, float& s11, float& s22, float& s12,
    float4* __restrict__ AB, float* __restrict__ C)
{
    #pragma unroll
    for (int j = 0; j < NR; j++) {
        const int R = START + j;
        float v1, v2;
        if (FULL) {
            v1 = __ldg(p1 + R * IMG_W);
            v2 = __ldg(p2 + R * IMG_W);
        } else {
            bool ok = colok && (R < rowlim);
            v1 = ok ? __ldg(p1 + R * IMG_W) : 0.0f;
            v2 = ok ? __ldg(p2 + R * IMG_W) : 0.0f;
        }
        float x1 = fmaf(v1, k1, b1);
        float x2 = fmaf(v2, k2, b2);
        s1 += x1; s2 += x2;
        s11 = fmaf(x1, x1, s11);
        s22 = fmaf(x2, x2, s22);
        s12 = fmaf(x1, x2, s12);
        if (R >= WS - 1) {
            const int lr = (R - (WS - 1)) % OH;
            AB[lr * PAB + tid] = make_float4(s1 * wgt, s2 * wgt, s11 * wgt, s22 * wgt);
            C[lr * PC + tid]   = s12 * wgt;
            float o1 = r1[(R + 1) % WS];
            float o2 = r2[(R + 1) % WS];
            s1 -= o1; s2 -= o2;
            s11 = fmaf(-o1, o1, s11);
            s22 = fmaf(-o2, o2, s22);
            s12 = fmaf(-o1, o2, s12);
        }
        r1[R % WS] = x1;
        r2[R % WS] = x2;
    }
}

// ---------------- phase 2: branch-free horizontal windows ----------------
template<bool FULL>
__device__ __forceinline__ float hchunk(const float4* __restrict__ AB,
                                        const float* __restrict__ C,
                                        int r, int x0,
                                        bool rowok, int maxi,
                                        float thr, float U, float IS,
                                        float& okmin)
{
    const ulonglong2* ABr = (const ulonglong2*)(AB + r * PAB + x0);
    const float*      Cr  = C + r * PC + x0;

    // tree warmup over first 10 columns
    ull hm, hv; float hc;
    {
        ulonglong2 t0 = ABr[0], t1 = ABr[1], t2 = ABr[2], t3 = ABr[3], t4 = ABr[4];
        ulonglong2 t5 = ABr[5], t6 = ABr[6], t7 = ABr[7], t8 = ABr[8], t9 = ABr[9];
        ull m01 = f2add(t0.x, t1.x), m23 = f2add(t2.x, t3.x);
        ull m45 = f2add(t4.x, t5.x), m67 = f2add(t6.x, t7.x);
        ull m89 = f2add(t8.x, t9.x);
        hm = f2add(f2add(f2add(m01, m23), f2add(m45, m67)), m89);
        ull v01 = f2add(t0.y, t1.y), v23 = f2add(t2.y, t3.y);
        ull v45 = f2add(t4.y, t5.y), v67 = f2add(t6.y, t7.y);
        ull v89 = f2add(t8.y, t9.y);
        hv = f2add(f2add(f2add(v01, v23), f2add(v45, v67)), v89);
        float c01 = Cr[0] + Cr[1], c23 = Cr[2] + Cr[3];
        float c45 = Cr[4] + Cr[5], c67 = Cr[6] + Cr[7];
        float c89 = Cr[8] + Cr[9];
        hc = ((c01 + c23) + (c45 + c67)) + c89;
    }

    float acc = 0.0f;
    #pragma unroll
    for (int j = 0; j < CW; j++) {
        ulonglong2 t = ABr[j + WS - 1];
        float c = Cr[j + WS - 1];
        hm = f2add(hm, t.x); hv = f2add(hv, t.y); hc += c;

        ull v12 = f2fma(hm, hm ^ F2_SGN, hv);   // s - m*m
        float m1, m2, v1, v2;
        f2unpack(hm, m1, m2);
        f2unpack(v12, v1, v2);
        float cv = fmaf(-m1, m2, hc);

        // branch-free fast value (exact when window is saturated)
        float p = v1 * v2;
        float s = p * rsqrtf(p);                // sigma1*sigma2
        float fv = __fdividef(cv + 10.0f, s + 10.0f);

        float vmin = fminf(v1, v2);
        if (FULL) {
            okmin = fminf(okmin, vmin);
            acc += fv;
        } else {
            bool valid = rowok && (j < maxi);
            okmin = fminf(okmin, valid ? vmin : 3.4e38f);
            acc += valid ? fv : 0.0f;
        }

        ulonglong2 u = ABr[j];                  // tail re-read
        float cu = Cr[j];
        hm = f2fma(u.x, F2_NEG1, hm);
        hv = f2fma(u.y, F2_NEG1, hv);
        hc -= cu;
    }

    // chunk-level fallback: warp-uniform, never taken on this data
    if (!__all_sync(0xffffffffu, okmin > thr))
        acc = exact_chunk(AB, C, r, x0, rowok, maxi, thr, U, IS);
    return acc;
}

// ---------------- main body ----------------
template<bool FULL>
__device__ __forceinline__ float body(const float* __restrict__ p1,
                                      const float* __restrict__ p2,
                                      int tid, int ox0, int oy0, int rowlim,
                                      float4* __restrict__ AB,
                                      float* __restrict__ C)
{
    const float k1 = g_k1, b1 = g_b1, k2 = g_k2, b2 = g_b2;
    const float wgt = 1.0f / (float)(WS * WS);
    const float U = g_u, IS = g_invs, thr = g_thr;

    const int r  = tid / NCK;            // 0..11
    const int x0 = (tid % NCK) * CW;
    const int maxi = OUT_W - (ox0 + x0);
    const bool colok = FULL || (ox0 + tid < IMG_W);
    const bool p1ok = (tid < ICT);

    float r1[WS], r2[WS];
    float s1 = 0.f, s2 = 0.f, s11 = 0.f, s22 = 0.f, s12 = 0.f;
    float acc = 0.0f;
    float okmin = 3.4e38f;

    // chunk 0: rows 0..21
    if (p1ok)
        vchunk<OH + WS - 1, 0, FULL>(p1, p2, tid, rowlim, colok,
                                     k1, b1, k2, b2, wgt,
                                     r1, r2, s1, s2, s11, s22, s12, AB, C);
    __syncthreads();
    acc += hchunk<FULL>(AB, C, r, x0, oy0 + r < OUT_H, maxi, thr, U, IS, okmin);
    __syncthreads();

    // chunk 1: rows 22..33
    if (p1ok)
        vchunk<OH, OH + WS - 1, FULL>(p1, p2, tid, rowlim, colok,
                                      k1, b1, k2, b2, wgt,
                                      r1, r2, s1, s2, s11, s22, s12, AB, C);
    __syncthreads();
    acc += hchunk<FULL>(AB, C, r, x0, oy0 + OH + r < OUT_H, maxi, thr, U, IS, okmin);
    __syncthreads();

    // chunk 2: rows 34..45
    if (p1ok)
        vchunk<OH, 2 * OH + WS - 1, FULL>(p1, p2, tid, rowlim, colok,
                                          k1, b1, k2, b2, wgt,
                                          r1, r2, s1, s2, s11, s22, s12, AB, C);
    __syncthreads();
    acc += hchunk<FULL>(AB, C, r, x0, oy0 + 2 * OH + r < OUT_H, maxi, thr, U, IS, okmin);
    __syncthreads();

    // chunk 3: rows 46..57
    if (p1ok)
        vchunk<OH, 3 * OH + WS - 1, FULL>(p1, p2, tid, rowlim, colok,
                                          k1, b1, k2, b2, wgt,
                                          r1, r2, s1, s2, s11, s22, s12, AB, C);
    __syncthreads();
    acc += hchunk<FULL>(AB, C, r, x0, oy0 + 3 * OH + r < OUT_H, maxi, thr, U, IS, okmin);
    return acc;
}

__global__ __launch_bounds__(NTHR, 3)
void tmqi_k(const float* __restrict__ img1, const float* __restrict__ img2) {
    extern __shared__ char sm_[];
    float4* AB = (float4*)sm_;
    float*  C  = (float*)(sm_ + C_OFF);

    const int tid = threadIdx.x;
    const int ox0 = blockIdx.x * OWT;
    const int oy0 = blockIdx.y * SEGR;
    const int bz  = blockIdx.z;

    const float* p1 = img1 + (size_t)bz * IMG_H * IMG_W + (size_t)oy0 * IMG_W + ox0 + tid;
    const float* p2 = img2 + (size_t)bz * IMG_H * IMG_W + (size_t)oy0 * IMG_W + ox0 + tid;
    const int rowlim = IMG_H - oy0;

    const bool fullb = (blockIdx.x < GX - 1) && (oy0 + SEGR + WS - 1 <= IMG_H);

    float acc;
    if (fullb)
        acc = body<true>(p1, p2, tid, ox0, oy0, rowlim, AB, C);
    else
        acc = body<false>(p1, p2, tid, ox0, oy0, rowlim, AB, C);

    // --- block reduction (9 warps) ---
    #pragma unroll
    for (int o = 16; o; o >>= 1)
        acc += __shfl_down_sync(0xffffffffu, acc, o);
    __shared__ float red[9];
    if ((tid & 31) == 0) red[tid >> 5] = acc;
    __syncthreads();
    if (tid == 0) {
        float v = red[0];
        #pragma unroll
        for (int i = 1; i < 9; i++) v += red[i];
        atomicAdd(&g_sum, (double)v);
    }
}

__global__ void final_k(float* out) {
    out[0] = (float)(g_sum / ((double)IMG_N * OUT_H * OUT_W));
}

// ---------------- launch -----------------------------------------------
extern "C" void kernel_launch(void* const* d_in, const int* in_sizes, int n_in,
                              void* d_out, int out_size) {
    const float* img1 = (const float*)d_in[0];
    const float* img2 = (const float*)d_in[1];
    float* out = (float*)d_out;

    init_k<<<1, 1>>>();

    int n4 = (IMG_N * IMG_H * IMG_W) / 4;
    minmax_k<<<2048, 256>>>((const float4*)img1, (const float4*)img2, n4);

    prep_k<<<1, 1>>>();

    cudaFuncSetAttribute(tmqi_k, cudaFuncAttributeMaxDynamicSharedMemorySize,
                         SMEM_BYTES);
    dim3 grid(GX, GYS, IMG_N);   // (4, 22, 16) = 1408 blocks
    tmqi_k<<<grid, NTHR, SMEM_BYTES>>>(img1, img2);

    final_k<<<1, 1>>>(out);
}

// round 13
// speedup vs baseline: 1.2741x; 1.2264x over previous
#include <cuda_runtime.h>
#include <math.h>

#define IMG_N 16
#define IMG_H 1024
#define IMG_W 1024
#define WS    11
#define OUT_H (IMG_H - WS + 1)   // 1014
#define OUT_W (IMG_W - WS + 1)   // 1014

#define NTHR  288                // 9 warps
#define OH    16                 // output rows per chunk
#define NCHUNK 3                 // chunks per block (48 output rows)
#define SEGR  (OH * NCHUNK)      // 48
#define NCK   18                 // chunks per row (NTHR/OH)
#define CW    15                 // outputs per thread
#define OWT   (NCK * CW)         // 270 output cols per tile
#define ICT   (OWT + WS - 1)     // 280 input cols per tile
#define PAB   281                // float4 pitch
#define PC    290                // float pitch
#define GX    4                  // ceil(1014/270)
#define GYS   22                 // ceil(1014/48)
#define NBLK  (GX * GYS * IMG_N) // 1408

#define AB_BYTES (OH * PAB * 16)             // 71936
#define C_OFF    AB_BYTES
#define SMEM_BYTES (C_OFF + OH * PC * 4)     // 90496 -> 2 CTAs/SM

typedef unsigned long long ull;

// ---------------- packed f32x2 helpers (phase 2 only) ----------------
__device__ __forceinline__ ull f2add(ull a, ull b) {
    ull r; asm("add.rn.f32x2 %0, %1, %2;" : "=l"(r) : "l"(a), "l"(b)); return r;
}
__device__ __forceinline__ ull f2mul(ull a, ull b) {
    ull r; asm("mul.rn.f32x2 %0, %1, %2;" : "=l"(r) : "l"(a), "l"(b)); return r;
}
__device__ __forceinline__ ull f2fma(ull a, ull b, ull c) {
    ull r; asm("fma.rn.f32x2 %0, %1, %2, %3;" : "=l"(r) : "l"(a), "l"(b), "l"(c)); return r;
}
__device__ __forceinline__ void f2unpack(ull v, float& lo, float& hi) {
    asm("mov.b64 {%0, %1}, %2;" : "=f"(lo), "=f"(hi) : "l"(v));
}
#define F2_NEG1 0xBF800000BF800000ULL
#define F2_SGN  0x8000000080000000ULL

// ---------------- device globals ----------
__device__ unsigned g_min1u, g_max1u, g_min2u, g_max2u;
__device__ double   g_sum;
__device__ unsigned g_done;

__device__ __forceinline__ unsigned fenc(float f) {
    unsigned b = __float_as_uint(f);
    return (b & 0x80000000u) ? ~b : (b | 0x80000000u);
}
__device__ __forceinline__ float fdec(unsigned u) {
    unsigned b = (u & 0x80000000u) ? (u ^ 0x80000000u) : ~u;
    return __uint_as_float(b);
}

__global__ void init_k() {
    g_min1u = 0xFFFFFFFFu; g_max1u = 0u;
    g_min2u = 0xFFFFFFFFu; g_max2u = 0u;
    g_sum   = 0.0;
    g_done  = 0u;
}

// ---------------- pass 1: global min/max --------------------
__global__ void minmax_k(const float4* __restrict__ a,
                         const float4* __restrict__ b, int n4) {
    float mn1 =  3.4e38f, mx1 = -3.4e38f;
    float mn2 =  3.4e38f, mx2 = -3.4e38f;
    for (int i = blockIdx.x * blockDim.x + threadIdx.x; i < n4;
         i += gridDim.x * blockDim.x) {
        float4 v = a[i];
        mn1 = fminf(mn1, fminf(fminf(v.x, v.y), fminf(v.z, v.w)));
        mx1 = fmaxf(mx1, fmaxf(fmaxf(v.x, v.y), fmaxf(v.z, v.w)));
        float4 w = b[i];
        mn2 = fminf(mn2, fminf(fminf(w.x, w.y), fminf(w.z, w.w)));
        mx2 = fmaxf(mx2, fmaxf(fmaxf(w.x, w.y), fmaxf(w.z, w.w)));
    }
    #pragma unroll
    for (int o = 16; o; o >>= 1) {
        mn1 = fminf(mn1, __shfl_down_sync(0xffffffffu, mn1, o));
        mx1 = fmaxf(mx1, __shfl_down_sync(0xffffffffu, mx1, o));
        mn2 = fminf(mn2, __shfl_down_sync(0xffffffffu, mn2, o));
        mx2 = fmaxf(mx2, __shfl_down_sync(0xffffffffu, mx2, o));
    }
    __shared__ float s0[8], s1[8], s2[8], s3[8];
    int lane = threadIdx.x & 31, warp = threadIdx.x >> 5;
    if (lane == 0) { s0[warp] = mn1; s1[warp] = mx1; s2[warp] = mn2; s3[warp] = mx2; }
    __syncthreads();
    if (threadIdx.x == 0) {
        for (int w = 1; w < 8; w++) {
            mn1 = fminf(mn1, s0[w]); mx1 = fmaxf(mx1, s1[w]);
            mn2 = fminf(mn2, s2[w]); mx2 = fmaxf(mx2, s3[w]);
        }
        atomicMin(&g_min1u, fenc(mn1)); atomicMax(&g_max1u, fenc(mx1));
        atomicMin(&g_min2u, fenc(mn2)); atomicMax(&g_max2u, fenc(mx2));
    }
}

// ---------------- exact per-pixel (fallback only) ----------------
__device__ float px_exact(float v1, float v2, float cv,
                          float thr, float U, float IS) {
    if (fminf(v1, v2) > thr) {
        float p = (v1 + 1e-6f) * (v2 + 1e-6f);
        float s = p * rsqrtf(p);
        return __fdividef(cv + 10.0f, s + 10.0f);
    }
    float sg1 = sqrtf(fmaxf(v1, 0.0f) + 1e-6f);
    float sg2 = sqrtf(fmaxf(v2, 0.0f) + 1e-6f);
    float pA = 0.5f * (1.0f + erff((sg1 - U) * IS));
    float pB = 0.5f * (1.0f + erff((sg2 - U) * IS));
    float num = 2.0f * pA * pB + 0.01f;
    float den = pA * pA + pB * pB + 0.01f;
    return (num / den) * ((cv + 10.0f) / (sg1 * sg2 + 10.0f));
}

// exact chunk recompute (never taken on this data); smem holds RAW sums
__device__ __noinline__ float exact_chunk(const float4* __restrict__ AB,
                                          const float* __restrict__ C,
                                          int r, int x0, bool rowok, int maxi,
                                          float wgt,
                                          float thr, float U, float IS) {
    float acc = 0.0f;
    if (!rowok) return 0.0f;
    for (int j = 0; j < CW; j++) {
        if (j >= maxi) break;
        float h0 = 0.f, h1 = 0.f, h2 = 0.f, h3 = 0.f, h4 = 0.f;
        for (int k = 0; k < WS; k++) {
            float4 t = AB[r * PAB + x0 + j + k];
            h0 += t.x; h1 += t.y; h2 += t.z; h3 += t.w;
            h4 += C[r * PC + x0 + j + k];
        }
        float m1 = h0 * wgt, m2 = h1 * wgt;
        float v1 = fmaf(-m1, m1, h2 * wgt);
        float v2 = fmaf(-m2, m2, h3 * wgt);
        float cv = fmaf(-m1, m2, h4 * wgt);
        acc += px_exact(v1, v2, cv, thr, U, IS);
    }
    return acc;
}

// ---------------- phase 1: streamed vertical chunk (raw sums) ----------
template<int NR, int START, bool FULL>
__device__ __forceinline__ void vchunk(
    const float* __restrict__ p1, const float* __restrict__ p2,
    int tid, int rowlim, bool colok,
    float k1, float b1, float k2, float b2,
    float (&r1)[WS], float (&r2)[WS],
    float& s1, float& s2, float& s11, float& s22, float& s12,
    float4* __restrict__ AB, float* __restrict__ C)
{
    #pragma unroll
    for (int j = 0; j < NR; j++) {
        const int R = START + j;
        float v1, v2;
        if (FULL) {
            v1 = __ldg(p1 + R * IMG_W);
            v2 = __ldg(p2 + R * IMG_W);
        } else {
            bool ok = colok && (R < rowlim);
            v1 = ok ? __ldg(p1 + R * IMG_W) : 0.0f;
            v2 = ok ? __ldg(p2 + R * IMG_W) : 0.0f;
        }
        float x1 = fmaf(v1, k1, b1);
        float x2 = fmaf(v2, k2, b2);
        s1 += x1; s2 += x2;
        s11 = fmaf(x1, x1, s11);
        s22 = fmaf(x2, x2, s22);
        s12 = fmaf(x1, x2, s12);
        if (R >= WS - 1) {
            const int lr = (R - (WS - 1)) % OH;
            AB[lr * PAB + tid] = make_float4(s1, s2, s11, s22);
            C[lr * PC + tid]   = s12;
            float o1 = r1[(R + 1) % WS];
            float o2 = r2[(R + 1) % WS];
            s1 -= o1; s2 -= o2;
            s11 = fmaf(-o1, o1, s11);
            s22 = fmaf(-o2, o2, s22);
            s12 = fmaf(-o1, o2, s12);
        }
        r1[R % WS] = x1;
        r2[R % WS] = x2;
    }
}

// ---------------- phase 2: branch-free horizontal windows ----------------
template<bool FULL>
__device__ __forceinline__ float hchunk(const float4* __restrict__ AB,
                                        const float* __restrict__ C,
                                        int r, int x0,
                                        bool rowok, int maxi,
                                        float wgt, ull wgt2,
                                        float thr, float U, float IS,
                                        float& okmin)
{
    const ulonglong2* ABr = (const ulonglong2*)(AB + r * PAB + x0);
    const float*      Cr  = C + r * PC + x0;

    // tree warmup over first 10 columns (raw sums)
    ull hm, hv; float hc;
    {
        ulonglong2 t0 = ABr[0], t1 = ABr[1], t2 = ABr[2], t3 = ABr[3], t4 = ABr[4];
        ulonglong2 t5 = ABr[5], t6 = ABr[6], t7 = ABr[7], t8 = ABr[8], t9 = ABr[9];
        ull m01 = f2add(t0.x, t1.x), m23 = f2add(t2.x, t3.x);
        ull m45 = f2add(t4.x, t5.x), m67 = f2add(t6.x, t7.x);
        ull m89 = f2add(t8.x, t9.x);
        hm = f2add(f2add(f2add(m01, m23), f2add(m45, m67)), m89);
        ull v01 = f2add(t0.y, t1.y), v23 = f2add(t2.y, t3.y);
        ull v45 = f2add(t4.y, t5.y), v67 = f2add(t6.y, t7.y);
        ull v89 = f2add(t8.y, t9.y);
        hv = f2add(f2add(f2add(v01, v23), f2add(v45, v67)), v89);
        float c01 = Cr[0] + Cr[1], c23 = Cr[2] + Cr[3];
        float c45 = Cr[4] + Cr[5], c67 = Cr[6] + Cr[7];
        float c89 = Cr[8] + Cr[9];
        hc = ((c01 + c23) + (c45 + c67)) + c89;
    }

    float acc = 0.0f;
    #pragma unroll
    for (int j = 0; j < CW; j++) {
        ulonglong2 t = ABr[j + WS - 1];
        float c = Cr[j + WS - 1];
        hm = f2add(hm, t.x); hv = f2add(hv, t.y); hc += c;

        ull mu12 = f2mul(hm, wgt2);                     // (mu1, mu2)
        ull v12  = f2fma(mu12, mu12 ^ F2_SGN, f2mul(hv, wgt2));
        float m1, m2, v1, v2;
        f2unpack(mu12, m1, m2);
        f2unpack(v12, v1, v2);
        float cv = fmaf(-m1, m2, hc * wgt);

        // branch-free fast value (exact when window is saturated)
        float p = v1 * v2;
        float s = p * rsqrtf(p);                // sigma1*sigma2
        float fv = __fdividef(cv + 10.0f, s + 10.0f);

        float vmin = fminf(v1, v2);
        if (FULL) {
            okmin = fminf(okmin, vmin);
            acc += fv;
        } else {
            bool valid = rowok && (j < maxi);
            okmin = fminf(okmin, valid ? vmin : 3.4e38f);
            acc += valid ? fv : 0.0f;
        }

        ulonglong2 u = ABr[j];                  // tail re-read
        float cu = Cr[j];
        hm = f2fma(u.x, F2_NEG1, hm);
        hv = f2fma(u.y, F2_NEG1, hv);
        hc -= cu;
    }

    // chunk-level fallback: warp-uniform, never taken on this data
    if (!__all_sync(0xffffffffu, okmin > thr))
        acc = exact_chunk(AB, C, r, x0, rowok, maxi, wgt, thr, U, IS);
    return acc;
}

// ---------------- main body ----------------
template<bool FULL>
__device__ __forceinline__ float body(const float* __restrict__ p1,
                                      const float* __restrict__ p2,
                                      int tid, int ox0, int oy0, int rowlim,
                                      float k1, float b1, float k2, float b2,
                                      float U, float IS, float thr,
                                      float4* __restrict__ AB,
                                      float* __restrict__ C)
{
    const float wgt = 1.0f / (float)(WS * WS);
    const ull wgt2 = ((ull)__float_as_uint(wgt) << 32) | __float_as_uint(wgt);

    const int r  = tid & 15;
    const int x0 = (tid >> 4) * CW;
    const int maxi = OUT_W - (ox0 + x0);
    const bool colok = FULL || (ox0 + tid < IMG_W);
    const bool p1ok = (tid < ICT);

    float r1[WS], r2[WS];
    float s1 = 0.f, s2 = 0.f, s11 = 0.f, s22 = 0.f, s12 = 0.f;
    float acc = 0.0f;
    float okmin = 3.4e38f;

    // chunk 0: rows 0..25
    if (p1ok)
        vchunk<OH + WS - 1, 0, FULL>(p1, p2, tid, rowlim, colok,
                                     k1, b1, k2, b2,
                                     r1, r2, s1, s2, s11, s22, s12, AB, C);
    __syncthreads();
    acc += hchunk<FULL>(AB, C, r, x0, oy0 + r < OUT_H, maxi,
                        wgt, wgt2, thr, U, IS, okmin);
    __syncthreads();

    // chunk 1: rows 26..41
    if (p1ok)
        vchunk<OH, OH + WS - 1, FULL>(p1, p2, tid, rowlim, colok,
                                      k1, b1, k2, b2,
                                      r1, r2, s1, s2, s11, s22, s12, AB, C);
    __syncthreads();
    acc += hchunk<FULL>(AB, C, r, x0, oy0 + OH + r < OUT_H, maxi,
                        wgt, wgt2, thr, U, IS, okmin);
    __syncthreads();

    // chunk 2: rows 42..57
    if (p1ok)
        vchunk<OH, 2 * OH + WS - 1, FULL>(p1, p2, tid, rowlim, colok,
                                          k1, b1, k2, b2,
                                          r1, r2, s1, s2, s11, s22, s12, AB, C);
    __syncthreads();
    acc += hchunk<FULL>(AB, C, r, x0, oy0 + 2 * OH + r < OUT_H, maxi,
                        wgt, wgt2, thr, U, IS, okmin);
    return acc;
}

__global__ __launch_bounds__(NTHR, 2)
void tmqi_k(const float* __restrict__ img1, const float* __restrict__ img2,
            float* __restrict__ out, float U, float IS, float thr) {
    extern __shared__ char sm_[];
    float4* AB = (float4*)sm_;
    float*  C  = (float*)(sm_ + C_OFF);

    const int tid = threadIdx.x;
    const int ox0 = blockIdx.x * OWT;
    const int oy0 = blockIdx.y * SEGR;
    const int bz  = blockIdx.z;

    // per-block normalization constants (redundant per thread; cheap)
    const float mn1 = fdec(g_min1u), mx1 = fdec(g_max1u);
    const float mn2 = fdec(g_min2u), mx2 = fdec(g_max2u);
    const float k1 = 255.0f / (mx1 - mn1 + 1e-6f);
    const float k2 = 255.0f / (mx2 - mn2 + 1e-6f);
    const float b1 = -mn1 * k1;
    const float b2 = -mn2 * k2;

    const float* p1 = img1 + (size_t)bz * IMG_H * IMG_W + (size_t)oy0 * IMG_W + ox0 + tid;
    const float* p2 = img2 + (size_t)bz * IMG_H * IMG_W + (size_t)oy0 * IMG_W + ox0 + tid;
    const int rowlim = IMG_H - oy0;

    const bool fullb = (blockIdx.x < GX - 1) && (oy0 + SEGR + WS - 1 <= IMG_H);

    float acc;
    if (fullb)
        acc = body<true>(p1, p2, tid, ox0, oy0, rowlim,
                         k1, b1, k2, b2, U, IS, thr, AB, C);
    else
        acc = body<false>(p1, p2, tid, ox0, oy0, rowlim,
                          k1, b1, k2, b2, U, IS, thr, AB, C);

    // --- block reduction (9 warps) ---
    #pragma unroll
    for (int o = 16; o; o >>= 1)
        acc += __shfl_down_sync(0xffffffffu, acc, o);
    __shared__ float red[9];
    if ((tid & 31) == 0) red[tid >> 5] = acc;
    __syncthreads();
    if (tid == 0) {
        float v = red[0];
        #pragma unroll
        for (int i = 1; i < 9; i++) v += red[i];
        atomicAdd(&g_sum, (double)v);
        __threadfence();
        unsigned prev = atomicAdd(&g_done, 1u);
        if (prev == NBLK - 1) {
            double s = atomicAdd(&g_sum, 0.0);   // ordered read via L2
            out[0] = (float)(s / ((double)IMG_N * OUT_H * OUT_W));
        }
    }
}

// ---------------- launch -----------------------------------------------
extern "C" void kernel_launch(void* const* d_in, const int* in_sizes, int n_in,
                              void* d_out, int out_size) {
    const float* img1 = (const float*)d_in[0];
    const float* img2 = (const float*)d_in[1];
    float* out = (float*)d_out;

    // TMQI constants (input-independent) in host double precision
    double csf = 100.0 * 2.6 * (0.0192 + 0.114 * 16.0) * exp(-pow(0.114 * 16.0, 1.1));
    double u   = 128.0 / (1.4 * csf);
    double sg  = u / 3.0;
    float  Uf  = (float)u;
    float  ISf = (float)(1.0 / (sg * sqrt(2.0)));
    double st  = u + 4.0 * sg * sqrt(2.0);    // erf arg >= 4 -> saturates to 1.0f
    float  thrf = (float)(st * st);

    init_k<<<1, 1>>>();

    int n4 = (IMG_N * IMG_H * IMG_W) / 4;
    minmax_k<<<2048, 256>>>((const float4*)img1, (const float4*)img2, n4);

    cudaFuncSetAttribute(tmqi_k, cudaFuncAttributeMaxDynamicSharedMemorySize,
                         SMEM_BYTES);
    dim3 grid(GX, GYS, IMG_N);   // (4, 22, 16) = 1408 blocks
    tmqi_k<<<grid, NTHR, SMEM_BYTES>>>(img1, img2, out, Uf, ISf, thrf);
}